// round 1
// baseline (speedup 1.0000x reference)
#include <cuda_runtime.h>
#include <cstddef>

#define N_NODES 50000
#define E_EDGES 600000
#define E_LABEL 200000
#define HD 128
#define FIN 768
#define NLAYERS 4

// ---------------- device scratch (no allocations allowed) ----------------
__device__ float g_xmq[2 * (size_t)N_NODES * HD];
__device__ float g_xsq[2 * (size_t)N_NODES * HD];
__device__ float g_agg[(size_t)N_NODES * HD];
__device__ int g_cnt_sq[N_NODES];
__device__ int g_cnt_mq[N_NODES];
__device__ int g_rp_sq[N_NODES + 1];
__device__ int g_rp_mq[N_NODES + 1];
__device__ int g_cur_sq[N_NODES];
__device__ int g_cur_mq[N_NODES];
__device__ int g_col_sq[E_EDGES];
__device__ int g_col_mq[E_EDGES];

// ---------------- CSR build ----------------
__global__ void count_edges(const int* __restrict__ src, const int* __restrict__ dst,
                            int* __restrict__ cnt_sq, int* __restrict__ cnt_mq) {
    int e = blockIdx.x * blockDim.x + threadIdx.x;
    if (e < E_EDGES) {
        atomicAdd(&cnt_sq[dst[e]], 1);
        atomicAdd(&cnt_mq[src[e]], 1);
    }
}

// Exclusive scan of two count arrays (block 0 -> sq, block 1 -> mq).
__global__ void scan2(const int* __restrict__ cntA, int* __restrict__ rpA, int* __restrict__ curA,
                      const int* __restrict__ cntB, int* __restrict__ rpB, int* __restrict__ curB) {
    const int* cnt = blockIdx.x ? cntB : cntA;
    int* rp  = blockIdx.x ? rpB  : rpA;
    int* cur = blockIdx.x ? curB : curA;
    const int n = N_NODES;
    __shared__ int wsum[32];
    int tid = threadIdx.x, lane = tid & 31, w = tid >> 5;
    int base = 0;
    for (int s = 0; s < n; s += 1024) {
        int i = s + tid;
        int v = (i < n) ? cnt[i] : 0;
        int x = v;
#pragma unroll
        for (int o = 1; o < 32; o <<= 1) {
            int t = __shfl_up_sync(0xffffffffu, x, o);
            if (lane >= o) x += t;
        }
        if (lane == 31) wsum[w] = x;
        __syncthreads();
        if (w == 0) {
            int y = wsum[lane];
#pragma unroll
            for (int o = 1; o < 32; o <<= 1) {
                int t = __shfl_up_sync(0xffffffffu, y, o);
                if (lane >= o) y += t;
            }
            wsum[lane] = y;
        }
        __syncthreads();
        int incl = x + (w ? wsum[w - 1] : 0);
        if (i < n) {
            int ex = base + incl - v;
            rp[i] = ex;
            cur[i] = ex;
        }
        base += wsum[31];
        __syncthreads();
    }
    if (tid == 0) rp[n] = base;
}

__global__ void fill_edges(const int* __restrict__ src, const int* __restrict__ dst,
                           int* __restrict__ cur_sq, int* __restrict__ cur_mq,
                           int* __restrict__ col_sq, int* __restrict__ col_mq) {
    int e = blockIdx.x * blockDim.x + threadIdx.x;
    if (e < E_EDGES) {
        int s = src[e], d = dst[e];
        col_sq[atomicAdd(&cur_sq[d], 1)] = s;   // neighbors (mq ids) of sq node d
        col_mq[atomicAdd(&cur_mq[s], 1)] = d;   // neighbors (sq ids) of mq node s
    }
}

// ---------------- mean aggregation: one warp per destination node ----------------
__global__ void aggregate(const float* __restrict__ x, const int* __restrict__ rp,
                          const int* __restrict__ col, float* __restrict__ out) {
    int wid = (blockIdx.x * blockDim.x + threadIdx.x) >> 5;
    int lane = threadIdx.x & 31;
    if (wid >= N_NODES) return;
    int beg = rp[wid], end = rp[wid + 1];
    float ax = 0.f, ay = 0.f, az = 0.f, aw = 0.f;
    int j = beg;
    for (; j + 4 <= end; j += 4) {
        int s0 = col[j], s1 = col[j + 1], s2 = col[j + 2], s3 = col[j + 3];
        float4 v0 = *(const float4*)&x[(size_t)s0 * HD + lane * 4];
        float4 v1 = *(const float4*)&x[(size_t)s1 * HD + lane * 4];
        float4 v2 = *(const float4*)&x[(size_t)s2 * HD + lane * 4];
        float4 v3 = *(const float4*)&x[(size_t)s3 * HD + lane * 4];
        ax += v0.x + v1.x + v2.x + v3.x;
        ay += v0.y + v1.y + v2.y + v3.y;
        az += v0.z + v1.z + v2.z + v3.z;
        aw += v0.w + v1.w + v2.w + v3.w;
    }
    for (; j < end; j++) {
        int s = col[j];
        float4 v = *(const float4*)&x[(size_t)s * HD + lane * 4];
        ax += v.x; ay += v.y; az += v.z; aw += v.w;
    }
    float inv = (end > beg) ? 1.0f / (float)(end - beg) : 0.f;
    float4 o = make_float4(ax * inv, ay * inv, az * inv, aw * inv);
    *(float4*)&out[(size_t)wid * HD + lane * 4] = o;
}

// ---------------- fused GEMM: C = A1@W1^T (+ A2@W2^T) + bias (+ addMat row) [+relu] ----
// A: [M, K] row-major. W: [128, K] row-major. C: [M, 128].
#define BM 128
#define BN 128
#define BK 8
#define TM 8
#define TN 8

__global__ __launch_bounds__(256) void gemm_fused(
    const float* __restrict__ A1, const float* __restrict__ W1, int K1,
    const float* __restrict__ A2, const float* __restrict__ W2, int K2,
    const float* __restrict__ bias,
    const float* __restrict__ addMat,
    float* __restrict__ C, int M, int relu) {
    __shared__ float As[BK][BM];
    __shared__ float Bs[BK][BN];
    int tid = threadIdx.x;
    int tx = tid & 15;        // 0..15 -> N
    int ty = tid >> 4;        // 0..15 -> M
    int mBase = blockIdx.x * BM;
    int r = tid >> 1;         // 0..127 : row (A) / n (W) for loads
    int q = (tid & 1) * 4;    // 0 or 4 : k offset for loads

    float acc[TM][TN];
#pragma unroll
    for (int i = 0; i < TM; i++)
#pragma unroll
        for (int jj = 0; jj < TN; jj++) acc[i][jj] = 0.f;

    const float* Aseg[2] = {A1, A2};
    const float* Wseg[2] = {W1, W2};
    int Kseg[2] = {K1, K2};

    for (int seg = 0; seg < 2; seg++) {
        const float* A = Aseg[seg];
        if (A == nullptr) continue;
        const float* W = Wseg[seg];
        int K = Kseg[seg];
        int mA = mBase + r;
        const float* arow = (mA < M) ? &A[(size_t)mA * K] : nullptr;
        const float* wrow = &W[(size_t)r * K];
        for (int k0 = 0; k0 < K; k0 += BK) {
            float4 av = arow ? *(const float4*)&arow[k0 + q] : make_float4(0.f, 0.f, 0.f, 0.f);
            float4 wv = *(const float4*)&wrow[k0 + q];
            As[q + 0][r] = av.x; As[q + 1][r] = av.y; As[q + 2][r] = av.z; As[q + 3][r] = av.w;
            Bs[q + 0][r] = wv.x; Bs[q + 1][r] = wv.y; Bs[q + 2][r] = wv.z; Bs[q + 3][r] = wv.w;
            __syncthreads();
#pragma unroll
            for (int kk = 0; kk < BK; kk++) {
                float4 a0 = *(const float4*)&As[kk][ty * TM];
                float4 a1 = *(const float4*)&As[kk][ty * TM + 4];
                float4 b0 = *(const float4*)&Bs[kk][tx * TN];
                float4 b1 = *(const float4*)&Bs[kk][tx * TN + 4];
                float a[TM] = {a0.x, a0.y, a0.z, a0.w, a1.x, a1.y, a1.z, a1.w};
                float b[TN] = {b0.x, b0.y, b0.z, b0.w, b1.x, b1.y, b1.z, b1.w};
#pragma unroll
                for (int i = 0; i < TM; i++)
#pragma unroll
                    for (int jj = 0; jj < TN; jj++) acc[i][jj] += a[i] * b[jj];
            }
            __syncthreads();
        }
    }

    // epilogue
    float bv[TN];
#pragma unroll
    for (int jj = 0; jj < TN; jj++) bv[jj] = bias[tx * TN + jj];
#pragma unroll
    for (int i = 0; i < TM; i++) {
        int m = mBase + ty * TM + i;
        if (m >= M) continue;
        float v[TN];
#pragma unroll
        for (int jj = 0; jj < TN; jj++) v[jj] = acc[i][jj] + bv[jj];
        if (addMat) {
            const float4* ar = (const float4*)&addMat[(size_t)m * HD + tx * TN];
            float4 m0 = ar[0], m1 = ar[1];
            v[0] += m0.x; v[1] += m0.y; v[2] += m0.z; v[3] += m0.w;
            v[4] += m1.x; v[5] += m1.y; v[6] += m1.z; v[7] += m1.w;
        }
        if (relu) {
#pragma unroll
            for (int jj = 0; jj < TN; jj++) v[jj] = fmaxf(v[jj], 0.f);
        }
        float4 o0 = make_float4(v[0], v[1], v[2], v[3]);
        float4 o1 = make_float4(v[4], v[5], v[6], v[7]);
        float4* cr = (float4*)&C[(size_t)m * HD + tx * TN];
        cr[0] = o0;
        cr[1] = o1;
    }
}

// ---------------- classifier: one warp per supervision edge ----------------
__global__ void classify(const float* __restrict__ xm, const float* __restrict__ xs,
                         const int* __restrict__ eli, float* __restrict__ out) {
    int wid = (blockIdx.x * blockDim.x + threadIdx.x) >> 5;
    int lane = threadIdx.x & 31;
    if (wid >= E_LABEL) return;
    int a = eli[wid];
    int b = eli[E_LABEL + wid];
    float4 u = *(const float4*)&xm[(size_t)a * HD + lane * 4];
    float4 v = *(const float4*)&xs[(size_t)b * HD + lane * 4];
    float s = u.x * v.x + u.y * v.y + u.z * v.z + u.w * v.w;
#pragma unroll
    for (int o = 16; o; o >>= 1) s += __shfl_xor_sync(0xffffffffu, s, o);
    if (lane == 0) out[wid] = s;
}

// ---------------- launch ----------------
extern "C" void kernel_launch(void* const* d_in, const int* in_sizes, int n_in,
                              void* d_out, int out_size) {
    // inputs per metadata order (mq_node_id / sq_node_id are identity arange -> unused)
    const float* sq_x      = (const float*)d_in[2];
    const int*   edge_idx  = (const int*)d_in[3];
    const int*   eli       = (const int*)d_in[4];
    const float* user_emb  = (const float*)d_in[5];
    const float* movie_emb = (const float*)d_in[6];
    const float* lin_W     = (const float*)d_in[7];
    const float* lin_b     = (const float*)d_in[8];
    const float* Wl_s      = (const float*)d_in[9];
    const float* bl_s      = (const float*)d_in[10];
    const float* Wr_s      = (const float*)d_in[11];
    const float* Wl_m      = (const float*)d_in[12];
    const float* bl_m      = (const float*)d_in[13];
    const float* Wr_m      = (const float*)d_in[14];

    const int* src = edge_idx;            // mq ids
    const int* dst = edge_idx + E_EDGES;  // sq ids

    float *xmq, *xsq, *agg;
    int *cnt_sq, *cnt_mq, *rp_sq, *rp_mq, *cur_sq, *cur_mq, *col_sq, *col_mq;
    cudaGetSymbolAddress((void**)&xmq, g_xmq);
    cudaGetSymbolAddress((void**)&xsq, g_xsq);
    cudaGetSymbolAddress((void**)&agg, g_agg);
    cudaGetSymbolAddress((void**)&cnt_sq, g_cnt_sq);
    cudaGetSymbolAddress((void**)&cnt_mq, g_cnt_mq);
    cudaGetSymbolAddress((void**)&rp_sq, g_rp_sq);
    cudaGetSymbolAddress((void**)&rp_mq, g_rp_mq);
    cudaGetSymbolAddress((void**)&cur_sq, g_cur_sq);
    cudaGetSymbolAddress((void**)&cur_mq, g_cur_mq);
    cudaGetSymbolAddress((void**)&col_sq, g_col_sq);
    cudaGetSymbolAddress((void**)&col_mq, g_col_mq);

    float* xmq0 = xmq;
    float* xmq1 = xmq + (size_t)N_NODES * HD;
    float* xsq0 = xsq;
    float* xsq1 = xsq + (size_t)N_NODES * HD;

    const int EB = (E_EDGES + 255) / 256;
    const int GEMM_BLKS = (N_NODES + BM - 1) / BM;
    const int AGG_BLKS = (N_NODES * 32 + 255) / 256;
    const int CLS_BLKS = (E_LABEL * 32 + 255) / 256;

    // ---- CSR build ----
    cudaMemsetAsync(cnt_sq, 0, N_NODES * sizeof(int));
    cudaMemsetAsync(cnt_mq, 0, N_NODES * sizeof(int));
    count_edges<<<EB, 256>>>(src, dst, cnt_sq, cnt_mq);
    scan2<<<2, 1024>>>(cnt_sq, rp_sq, cur_sq, cnt_mq, rp_mq, cur_mq);
    fill_edges<<<EB, 256>>>(src, dst, cur_sq, cur_mq, col_sq, col_mq);

    // ---- input encoders ----
    // x_mq = user_emb (mq_node_id is arange)
    cudaMemcpyAsync(xmq0, user_emb, (size_t)N_NODES * HD * sizeof(float),
                    cudaMemcpyDeviceToDevice);
    // x_sq = sq_x @ lin_W^T + lin_b + movie_emb
    gemm_fused<<<GEMM_BLKS, 256>>>(sq_x, lin_W, FIN, nullptr, nullptr, 0,
                                   lin_b, movie_emb, xsq0, N_NODES, 0);

    float* xm = xmq0; float* xs = xsq0;
    float* xmn = xmq1; float* xsn = xsq1;
    for (int i = 0; i < NLAYERS; i++) {
        int relu = (i == 0) ? 1 : 0;
        // new_sq = mean(x_mq over in-edges) @ Wl_s^T + bl_s + x_sq @ Wr_s^T
        aggregate<<<AGG_BLKS, 256>>>(xm, rp_sq, col_sq, agg);
        gemm_fused<<<GEMM_BLKS, 256>>>(agg, Wl_s + (size_t)i * HD * HD, HD,
                                       xs, Wr_s + (size_t)i * HD * HD, HD,
                                       bl_s + (size_t)i * HD, nullptr, xsn, N_NODES, relu);
        // new_mq = mean(x_sq over out-edges) @ Wl_m^T + bl_m + x_mq @ Wr_m^T
        aggregate<<<AGG_BLKS, 256>>>(xs, rp_mq, col_mq, agg);
        gemm_fused<<<GEMM_BLKS, 256>>>(agg, Wl_m + (size_t)i * HD * HD, HD,
                                       xm, Wr_m + (size_t)i * HD * HD, HD,
                                       bl_m + (size_t)i * HD, nullptr, xmn, N_NODES, relu);
        float* t;
        t = xm; xm = xmn; xmn = t;
        t = xs; xs = xsn; xsn = t;
    }

    // ---- classifier ----
    classify<<<CLS_BLKS, 256>>>(xm, xs, eli, (float*)d_out);
}

// round 3
// speedup vs baseline: 1.5074x; 1.5074x over previous
#include <cuda_runtime.h>
#include <cuda_bf16.h>
#include <cstdint>
#include <cstddef>

#define N_NODES 50000
#define E_EDGES 600000
#define E_LABEL 200000
#define HD 128
#define FIN 768
#define NLAYERS 4

// ---------------- device scratch (no allocations allowed) ----------------
__device__ float g_xmq[2 * (size_t)N_NODES * HD];
__device__ float g_xsq[2 * (size_t)N_NODES * HD];
__device__ float g_agg[(size_t)N_NODES * HD];
__device__ int g_cnt_sq[N_NODES];
__device__ int g_cnt_mq[N_NODES];
__device__ int g_rp_sq[N_NODES + 1];
__device__ int g_rp_mq[N_NODES + 1];
__device__ int g_cur_sq[N_NODES];
__device__ int g_cur_mq[N_NODES];
__device__ int g_col_sq[E_EDGES];
__device__ int g_col_mq[E_EDGES];

// ================= helpers =================
__device__ __forceinline__ uint32_t smem_u32(const void* p) {
    uint32_t a;
    asm("{ .reg .u64 t; cvta.to.shared.u64 t, %1; cvt.u32.u64 %0, t; }" : "=r"(a) : "l"(p));
    return a;
}
__device__ __forceinline__ void ldsm_x4(uint32_t* r, uint32_t addr) {
    asm volatile("ldmatrix.sync.aligned.m8n8.x4.shared.b16 {%0,%1,%2,%3}, [%4];"
                 : "=r"(r[0]), "=r"(r[1]), "=r"(r[2]), "=r"(r[3]) : "r"(addr));
}
__device__ __forceinline__ void mma_bf16(float* d, const uint32_t* a, uint32_t b0, uint32_t b1) {
    asm volatile(
        "mma.sync.aligned.m16n8k16.row.col.f32.bf16.bf16.f32 "
        "{%0,%1,%2,%3},{%4,%5,%6,%7},{%8,%9},{%0,%1,%2,%3};"
        : "+f"(d[0]), "+f"(d[1]), "+f"(d[2]), "+f"(d[3])
        : "r"(a[0]), "r"(a[1]), "r"(a[2]), "r"(a[3]), "r"(b0), "r"(b1));
}
__device__ __forceinline__ uint32_t pack_bf2(float a, float b) {
    __nv_bfloat162 h = __floats2bfloat162_rn(a, b);
    return *reinterpret_cast<uint32_t*>(&h);
}

// ---------------- CSR build ----------------
__global__ void count_edges(const int* __restrict__ src, const int* __restrict__ dst,
                            int* __restrict__ cnt_sq, int* __restrict__ cnt_mq) {
    int e = blockIdx.x * blockDim.x + threadIdx.x;
    if (e < E_EDGES) {
        atomicAdd(&cnt_sq[dst[e]], 1);
        atomicAdd(&cnt_mq[src[e]], 1);
    }
}

__global__ void scan2(const int* __restrict__ cntA, int* __restrict__ rpA, int* __restrict__ curA,
                      const int* __restrict__ cntB, int* __restrict__ rpB, int* __restrict__ curB) {
    const int* cnt = blockIdx.x ? cntB : cntA;
    int* rp  = blockIdx.x ? rpB  : rpA;
    int* cur = blockIdx.x ? curB : curA;
    const int n = N_NODES;
    __shared__ int wsum[32];
    int tid = threadIdx.x, lane = tid & 31, w = tid >> 5;
    int base = 0;
    for (int s = 0; s < n; s += 1024) {
        int i = s + tid;
        int v = (i < n) ? cnt[i] : 0;
        int x = v;
#pragma unroll
        for (int o = 1; o < 32; o <<= 1) {
            int t = __shfl_up_sync(0xffffffffu, x, o);
            if (lane >= o) x += t;
        }
        if (lane == 31) wsum[w] = x;
        __syncthreads();
        if (w == 0) {
            int y = wsum[lane];
#pragma unroll
            for (int o = 1; o < 32; o <<= 1) {
                int t = __shfl_up_sync(0xffffffffu, y, o);
                if (lane >= o) y += t;
            }
            wsum[lane] = y;
        }
        __syncthreads();
        int incl = x + (w ? wsum[w - 1] : 0);
        if (i < n) {
            int ex = base + incl - v;
            rp[i] = ex;
            cur[i] = ex;
        }
        base += wsum[31];
        __syncthreads();
    }
    if (tid == 0) rp[n] = base;
}

__global__ void fill_edges(const int* __restrict__ src, const int* __restrict__ dst,
                           int* __restrict__ cur_sq, int* __restrict__ cur_mq,
                           int* __restrict__ col_sq, int* __restrict__ col_mq) {
    int e = blockIdx.x * blockDim.x + threadIdx.x;
    if (e < E_EDGES) {
        int s = src[e], d = dst[e];
        col_sq[atomicAdd(&cur_sq[d], 1)] = s;
        col_mq[atomicAdd(&cur_mq[s], 1)] = d;
    }
}

// ---------------- mean aggregation: one warp per destination node ----------------
__global__ void aggregate(const float* __restrict__ x, const int* __restrict__ rp,
                          const int* __restrict__ col, float* __restrict__ out) {
    int wid = (blockIdx.x * blockDim.x + threadIdx.x) >> 5;
    int lane = threadIdx.x & 31;
    if (wid >= N_NODES) return;
    int beg = rp[wid], end = rp[wid + 1];
    float ax = 0.f, ay = 0.f, az = 0.f, aw = 0.f;
    int j = beg;
    for (; j + 4 <= end; j += 4) {
        int s0 = col[j], s1 = col[j + 1], s2 = col[j + 2], s3 = col[j + 3];
        float4 v0 = *(const float4*)&x[(size_t)s0 * HD + lane * 4];
        float4 v1 = *(const float4*)&x[(size_t)s1 * HD + lane * 4];
        float4 v2 = *(const float4*)&x[(size_t)s2 * HD + lane * 4];
        float4 v3 = *(const float4*)&x[(size_t)s3 * HD + lane * 4];
        ax += v0.x + v1.x + v2.x + v3.x;
        ay += v0.y + v1.y + v2.y + v3.y;
        az += v0.z + v1.z + v2.z + v3.z;
        aw += v0.w + v1.w + v2.w + v3.w;
    }
    for (; j < end; j++) {
        int s = col[j];
        float4 v = *(const float4*)&x[(size_t)s * HD + lane * 4];
        ax += v.x; ay += v.y; az += v.z; aw += v.w;
    }
    float inv = (end > beg) ? 1.0f / (float)(end - beg) : 0.f;
    float4 o = make_float4(ax * inv, ay * inv, az * inv, aw * inv);
    *(float4*)&out[(size_t)wid * HD + lane * 4] = o;
}

// ---------------- mma.sync fused GEMM -------------------------------------
// C[M,128] = A1[M,K1]@W1[128,K1]^T (+ A2@W2^T) + bias (+ addMat) [+relu]
// bf16 hi/lo split, 3-pass warp MMA (m16n8k16), fp32 register accumulation.
// CTA tile 128x128; 8 warps as 4(M) x 2(N); warp tile 32x64; K-chunk 32.
#define BKC 32
#define SST 40   // smem row stride in bf16 elems (80 B: conflict-free ldmatrix)

__global__ __launch_bounds__(256) void gemm_mma(
    const float* __restrict__ A1, const float* __restrict__ W1, int K1,
    const float* __restrict__ A2, const float* __restrict__ W2, int K2,
    const float* __restrict__ bias,
    const float* __restrict__ addMat,
    float* __restrict__ C, int M, int relu) {
    __shared__ __align__(16) __nv_bfloat16 sAh[128 * SST];
    __shared__ __align__(16) __nv_bfloat16 sAl[128 * SST];
    __shared__ __align__(16) __nv_bfloat16 sWh[128 * SST];
    __shared__ __align__(16) __nv_bfloat16 sWl[128 * SST];

    const int tid = threadIdx.x;
    const int wid = tid >> 5, lane = tid & 31;
    const int wm = wid & 3;      // M group (32 rows)
    const int wn = wid >> 2;     // N group (64 cols)

    const uint32_t bAh = smem_u32(sAh), bAl = smem_u32(sAl);
    const uint32_t bWh = smem_u32(sWh), bWl = smem_u32(sWl);

    // loader assignment: row r, 16 consecutive k-cols
    const int lr = tid >> 1;
    const int lc = (tid & 1) * 16;
    const int mrow = blockIdx.x * 128 + lr;

    // ldmatrix lane addressing (element indices)
    const int aRow = wm * 32 + (lane & 15);          // + mi*16
    const int aColSeg = (lane >> 4) * 8;             // + kstep
    const int bRow = wn * 64 + ((lane >> 4) & 1) * 8 + (lane & 7);  // + p*16
    const int bColSeg = ((lane >> 3) & 1) * 8;       // + kstep

    float acc[2][8][4];
#pragma unroll
    for (int i = 0; i < 2; i++)
#pragma unroll
        for (int j = 0; j < 8; j++)
#pragma unroll
            for (int q = 0; q < 4; q++) acc[i][j][q] = 0.f;

    const float* Aseg[2] = {A1, A2};
    const float* Wseg[2] = {W1, W2};
    const int Kseg[2] = {K1, K2};

    for (int seg = 0; seg < 2; seg++) {
        const float* A = Aseg[seg];
        if (A == nullptr) continue;
        const float* W = Wseg[seg];
        const int K = Kseg[seg];
        const float* arow = (mrow < M) ? A + (size_t)mrow * K + lc : nullptr;
        const float* wrow = W + (size_t)lr * K + lc;
        for (int k0 = 0; k0 < K; k0 += BKC) {
            // ---- convert fp32 -> bf16 hi/lo into SMEM ----
            {
                uint32_t soff = (uint32_t)(lr * SST + lc);
#pragma unroll
                for (int j = 0; j < 4; j++) {
                    float4 f = arow ? *(const float4*)(arow + k0 + j * 4)
                                    : make_float4(0.f, 0.f, 0.f, 0.f);
                    float hx = __bfloat162float(__float2bfloat16(f.x));
                    float hy = __bfloat162float(__float2bfloat16(f.y));
                    float hz = __bfloat162float(__float2bfloat16(f.z));
                    float hw = __bfloat162float(__float2bfloat16(f.w));
                    *(uint2*)&sAh[soff + j * 4] = make_uint2(pack_bf2(hx, hy), pack_bf2(hz, hw));
                    *(uint2*)&sAl[soff + j * 4] =
                        make_uint2(pack_bf2(f.x - hx, f.y - hy), pack_bf2(f.z - hz, f.w - hw));
                    float4 g = *(const float4*)(wrow + k0 + j * 4);
                    float gx = __bfloat162float(__float2bfloat16(g.x));
                    float gy = __bfloat162float(__float2bfloat16(g.y));
                    float gz = __bfloat162float(__float2bfloat16(g.z));
                    float gw = __bfloat162float(__float2bfloat16(g.w));
                    *(uint2*)&sWh[soff + j * 4] = make_uint2(pack_bf2(gx, gy), pack_bf2(gz, gw));
                    *(uint2*)&sWl[soff + j * 4] =
                        make_uint2(pack_bf2(g.x - gx, g.y - gy), pack_bf2(g.z - gz, g.w - gw));
                }
            }
            __syncthreads();
            // ---- MMA over this chunk ----
#pragma unroll
            for (int kstep = 0; kstep < BKC; kstep += 16) {
                uint32_t ah[2][4], al[2][4];
#pragma unroll
                for (int mi = 0; mi < 2; mi++) {
                    uint32_t aoff = (uint32_t)((aRow + mi * 16) * SST + kstep + aColSeg) * 2;
                    ldsm_x4(ah[mi], bAh + aoff);
                    ldsm_x4(al[mi], bAl + aoff);
                }
#pragma unroll
                for (int p = 0; p < 4; p++) {
                    uint32_t boff = (uint32_t)((bRow + p * 16) * SST + kstep + bColSeg) * 2;
                    uint32_t bh[4], bl[4];
                    ldsm_x4(bh, bWh + boff);
                    ldsm_x4(bl, bWl + boff);
#pragma unroll
                    for (int mi = 0; mi < 2; mi++) {
                        float* d0 = acc[mi][p * 2 + 0];
                        float* d1 = acc[mi][p * 2 + 1];
                        mma_bf16(d0, ah[mi], bh[0], bh[1]);
                        mma_bf16(d1, ah[mi], bh[2], bh[3]);
                        mma_bf16(d0, ah[mi], bl[0], bl[1]);
                        mma_bf16(d1, ah[mi], bl[2], bl[3]);
                        mma_bf16(d0, al[mi], bh[0], bh[1]);
                        mma_bf16(d1, al[mi], bh[2], bh[3]);
                    }
                }
            }
            __syncthreads();
        }
    }

    // ---- epilogue ----
    const int rowBase = blockIdx.x * 128 + wm * 32 + (lane >> 2);
    const int colBase = wn * 64 + (lane & 3) * 2;
#pragma unroll
    for (int mi = 0; mi < 2; mi++) {
#pragma unroll
        for (int h = 0; h < 2; h++) {
            int m = rowBase + mi * 16 + h * 8;
            if (m >= M) continue;
            const float* amr = addMat ? &addMat[(size_t)m * HD] : nullptr;
            float* cr = &C[(size_t)m * HD];
#pragma unroll
            for (int nb = 0; nb < 8; nb++) {
                int c = colBase + nb * 8;
                float v0 = acc[mi][nb][h * 2 + 0] + __ldg(&bias[c]);
                float v1 = acc[mi][nb][h * 2 + 1] + __ldg(&bias[c + 1]);
                if (amr) {
                    float2 a2 = *(const float2*)(amr + c);
                    v0 += a2.x; v1 += a2.y;
                }
                if (relu) { v0 = fmaxf(v0, 0.f); v1 = fmaxf(v1, 0.f); }
                *(float2*)(cr + c) = make_float2(v0, v1);
            }
        }
    }
}

// ---------------- classifier: one warp per supervision edge ----------------
__global__ void classify(const float* __restrict__ xm, const float* __restrict__ xs,
                         const int* __restrict__ eli, float* __restrict__ out) {
    int wid = (blockIdx.x * blockDim.x + threadIdx.x) >> 5;
    int lane = threadIdx.x & 31;
    if (wid >= E_LABEL) return;
    int a = eli[wid];
    int b = eli[E_LABEL + wid];
    float4 u = *(const float4*)&xm[(size_t)a * HD + lane * 4];
    float4 v = *(const float4*)&xs[(size_t)b * HD + lane * 4];
    float s = u.x * v.x + u.y * v.y + u.z * v.z + u.w * v.w;
#pragma unroll
    for (int o = 16; o; o >>= 1) s += __shfl_xor_sync(0xffffffffu, s, o);
    if (lane == 0) out[wid] = s;
}

// ---------------- launch ----------------
extern "C" void kernel_launch(void* const* d_in, const int* in_sizes, int n_in,
                              void* d_out, int out_size) {
    const float* sq_x      = (const float*)d_in[2];
    const int*   edge_idx  = (const int*)d_in[3];
    const int*   eli       = (const int*)d_in[4];
    const float* user_emb  = (const float*)d_in[5];
    const float* movie_emb = (const float*)d_in[6];
    const float* lin_W     = (const float*)d_in[7];
    const float* lin_b     = (const float*)d_in[8];
    const float* Wl_s      = (const float*)d_in[9];
    const float* bl_s      = (const float*)d_in[10];
    const float* Wr_s      = (const float*)d_in[11];
    const float* Wl_m      = (const float*)d_in[12];
    const float* bl_m      = (const float*)d_in[13];
    const float* Wr_m      = (const float*)d_in[14];

    const int* src = edge_idx;
    const int* dst = edge_idx + E_EDGES;

    float *xmq, *xsq, *agg;
    int *cnt_sq, *cnt_mq, *rp_sq, *rp_mq, *cur_sq, *cur_mq, *col_sq, *col_mq;
    cudaGetSymbolAddress((void**)&xmq, g_xmq);
    cudaGetSymbolAddress((void**)&xsq, g_xsq);
    cudaGetSymbolAddress((void**)&agg, g_agg);
    cudaGetSymbolAddress((void**)&cnt_sq, g_cnt_sq);
    cudaGetSymbolAddress((void**)&cnt_mq, g_cnt_mq);
    cudaGetSymbolAddress((void**)&rp_sq, g_rp_sq);
    cudaGetSymbolAddress((void**)&rp_mq, g_rp_mq);
    cudaGetSymbolAddress((void**)&cur_sq, g_cur_sq);
    cudaGetSymbolAddress((void**)&cur_mq, g_cur_mq);
    cudaGetSymbolAddress((void**)&col_sq, g_col_sq);
    cudaGetSymbolAddress((void**)&col_mq, g_col_mq);

    float* xmq0 = xmq;
    float* xmq1 = xmq + (size_t)N_NODES * HD;
    float* xsq0 = xsq;
    float* xsq1 = xsq + (size_t)N_NODES * HD;

    const int EB = (E_EDGES + 255) / 256;
    const int GEMM_BLKS = (N_NODES + 127) / 128;
    const int AGG_BLKS = (N_NODES * 32 + 255) / 256;
    const int CLS_BLKS = (E_LABEL * 32 + 255) / 256;

    // ---- CSR build ----
    cudaMemsetAsync(cnt_sq, 0, N_NODES * sizeof(int));
    cudaMemsetAsync(cnt_mq, 0, N_NODES * sizeof(int));
    count_edges<<<EB, 256>>>(src, dst, cnt_sq, cnt_mq);
    scan2<<<2, 1024>>>(cnt_sq, rp_sq, cur_sq, cnt_mq, rp_mq, cur_mq);
    fill_edges<<<EB, 256>>>(src, dst, cur_sq, cur_mq, col_sq, col_mq);

    // ---- input encoders ----
    cudaMemcpyAsync(xmq0, user_emb, (size_t)N_NODES * HD * sizeof(float),
                    cudaMemcpyDeviceToDevice);
    gemm_mma<<<GEMM_BLKS, 256>>>(sq_x, lin_W, FIN, nullptr, nullptr, 0,
                                 lin_b, movie_emb, xsq0, N_NODES, 0);

    float* xm = xmq0; float* xs = xsq0;
    float* xmn = xmq1; float* xsn = xsq1;
    for (int i = 0; i < NLAYERS; i++) {
        int relu = (i == 0) ? 1 : 0;
        aggregate<<<AGG_BLKS, 256>>>(xm, rp_sq, col_sq, agg);
        gemm_mma<<<GEMM_BLKS, 256>>>(agg, Wl_s + (size_t)i * HD * HD, HD,
                                     xs, Wr_s + (size_t)i * HD * HD, HD,
                                     bl_s + (size_t)i * HD, nullptr, xsn, N_NODES, relu);
        aggregate<<<AGG_BLKS, 256>>>(xs, rp_mq, col_mq, agg);
        gemm_mma<<<GEMM_BLKS, 256>>>(agg, Wl_m + (size_t)i * HD * HD, HD,
                                     xm, Wr_m + (size_t)i * HD * HD, HD,
                                     bl_m + (size_t)i * HD, nullptr, xmn, N_NODES, relu);
        float* t;
        t = xm; xm = xmn; xmn = t;
        t = xs; xs = xsn; xsn = t;
    }

    classify<<<CLS_BLKS, 256>>>(xm, xs, eli, (float*)d_out);
}